// round 11
// baseline (speedup 1.0000x reference)
#include <cuda_runtime.h>
#include <cuda_fp16.h>
#include <cstdint>

#define Bb     2
#define CIN    32
#define COUT   64
#define KK     9
#define HH     256
#define WW     512
#define HWSZ   (HH*WW)        // 131072
#define OHW    (HH*WW)        // 131072
#define CK     (CIN*KK)       // 288
#define NKS    (CK/8)         // 36

#define TPIX   16             // pixels per tile
#define NCOLS  32             // gemm N = 16 pix * 2 batch
#define SLW    36             // sB word stride (36%32==4 -> conflict-free frag reads)
#define NTHR   128

// scratch: x transposed to [B, H*W, C] in fp16 ; weights in tf32 mma-fragment layout
__device__ __align__(16) uint2 g_xt2[(size_t)Bb*HWSZ*CIN/4 + 16];   // uint2 = 4 halves
__device__ __align__(16) float g_wfrag[COUT*CK];

__device__ __forceinline__ uint32_t f2tf32(float v) {
    uint32_t u;
    asm("cvt.rna.tf32.f32 %0, %1;" : "=r"(u) : "f"(v));
    return u;
}
__device__ __forceinline__ uint32_t h2u(__half2 h) {
    union { __half2 h; uint32_t u; } c; c.h = h; return c.u;
}
__device__ __forceinline__ float4 h8f4(uint2 r) {
    union { uint32_t u; __half2 h; } a, b; a.u = r.x; b.u = r.y;
    float2 lo = __half22float2(a.h);
    float2 hi = __half22float2(b.h);
    return make_float4(lo.x, lo.y, hi.x, hi.y);
}

// ------- transpose x: [B,C,HW] -> fp16 [B,HW,C]; wt fragment bake on y==2 -------
__global__ void transpose_kernel(const float* __restrict__ x,
                                 const float* __restrict__ w) {
    __shared__ float tile[32][36];
    int b   = blockIdx.y;
    int tid = threadIdx.x;
    if (b == 2) {
        // weights: W[o][c][k] -> tf32 A-frag layout [mg(4)][ks(36)][lane(32)][slot(4)]
        int i = blockIdx.x*256 + tid;
        if (i < COUT*CK) {
            int s    = i & 3;
            int lane = (i >> 2) & 31;
            int ks   = (i >> 7) % NKS;
            int mg   = i / (NKS*128);
            int o  = mg*16 + (lane >> 2) + (s & 1)*8;
            int ck = ks*8 + (lane & 3) + (s >> 1)*4;
            int c = ck & 31, k = ck >> 5;
            g_wfrag[i] = __uint_as_float(f2tf32(w[(o*CIN + c)*KK + k]));
        }
        return;
    }
    int hw0 = blockIdx.x * 32;
    {
        int c = tid >> 3, q = tid & 7;
        float4 v = ((const float4*)x)[(((size_t)(b*CIN + c))*HWSZ + hw0)/4 + q];
        *(float4*)&tile[c][q*4] = v;
    }
    __syncthreads();
    {
        int hw = tid & 31, cg = tid >> 5;     // cg 0..7 -> 4-channel group
        uint2 pk;
        pk.x = h2u(__floats2half2_rn(tile[cg*4+0][hw], tile[cg*4+1][hw]));
        pk.y = h2u(__floats2half2_rn(tile[cg*4+2][hw], tile[cg*4+3][hw]));
        g_xt2[((size_t)b*HWSZ + hw0 + hw)*8 + cg] = pk;
    }
}

// ---------------- main: deep-pipelined fp16 gather + tf32 mma.sync, 4 CTAs/SM ----------------
__global__ void __launch_bounds__(NTHR, 4)
mapped_conv_kernel(const float* __restrict__ bias,
                   const float* __restrict__ smap,
                   float* __restrict__ out)
{
    __shared__ float  sB[2*NCOLS*SLW];     // 2304 fl, double-buffered tf32 sampled tile
    __shared__ int2   sIdx2[TPIX*KK];      // 144: uint2-offsets of (y0,x0) and (y1,x0)
    __shared__ float4 sWgt4[TPIX*KK];      // 144
    __shared__ float  sBias[COUT];

    const int tid  = threadIdx.x;
    const int w    = tid >> 5;             // 0..3
    const int lane = tid & 31;
    const int pix0 = blockIdx.x * TPIX;

    if (tid < COUT) sBias[tid] = bias[tid];

    // bilinear tables: task t = p*9+k, 144 tasks
    for (int t = tid; t < TPIX*KK; t += NTHR) {
        int p = t / KK, k = t - p*KK;
        float2 sxy = ((const float2*)smap)[(pix0 + p)*KK + k];
        float bx = floorf(sxy.x), by = floorf(sxy.y);
        float fx = sxy.x - bx,    fy = sxy.y - by;
        int x0 = (int)bx, y0 = (int)by;
        int x0c = min(max(x0, 0), WW-2);   // +1 block always in-bounds; exact (fx>0 => x0<=510)
        int y0c = min(max(y0, 0), HH-1);
        int y1c = min(y0 + 1, HH-1);
        sIdx2[t] = make_int2((y0c*WW + x0c)*8, (y1c*WW + x0c)*8);
        sWgt4[t] = make_float4((1.f-fx)*(1.f-fy), fx*(1.f-fy),
                               (1.f-fx)*fy,       fx*fy);
    }

    // gather mapping: warp w -> 8 cols; col = b*16 + p ; lane = cq(8) x cs(4)
    const int gb_b  = w >> 1;
    const int gcol0 = w * 8;
    const int gp0   = (w & 1) * 8;
    const int cq    = lane & 7;            // 4-channel group (cq*4..+3)
    const int cs    = lane >> 3;
    const uint2* __restrict__ gx2 = g_xt2 + (size_t)gb_b*HWSZ*8 + cq;

    // mma mapping: warp = mw (rows mw*16..+15), all 32 cols
    const int mw = w;
    const uint32_t* sBu = (const uint32_t*)sB;
    uint32_t bOff[4];
#pragma unroll
    for (int g = 0; g < 4; g++)
        bOff[g] = (uint32_t)(g*8 + (lane >> 2))*SLW + (lane & 3);

    const uint4* __restrict__ gw4 = (const uint4*)g_wfrag + (uint32_t)(mw*NKS)*32 + lane;

    float d[4][4];
#pragma unroll
    for (int g = 0; g < 4; g++)
#pragma unroll
        for (int j = 0; j < 4; j++) d[g][j] = 0.f;

    uint2 vs[2][4];      // [col-iter][block: y0x0,y0x1,y1x0,y1x1]
    uint4 Acur[4], Anx[4];

    __syncthreads();     // tables ready

    // ---- prologue: gather+store tap 0; issue tap 1 loads; prefetch A(0)
#pragma unroll
    for (int i = 0; i < 2; i++) {
        int p = gp0 + i*4 + cs;
        int2 id = sIdx2[p*KK];
        vs[i][0] = gx2[id.x];
        vs[i][1] = gx2[id.x + 8];
        vs[i][2] = gx2[id.y];
        vs[i][3] = gx2[id.y + 8];
    }
#pragma unroll
    for (int ksl = 0; ksl < 4; ksl++) Anx[ksl] = gw4[ksl*32];
#pragma unroll
    for (int i = 0; i < 2; i++) {
        int p   = gp0 + i*4 + cs;
        int col = gcol0 + i*4 + cs;
        float4 wt = sWgt4[p*KK];
        float4 v0 = h8f4(vs[i][0]), v1 = h8f4(vs[i][1]);
        float4 v2 = h8f4(vs[i][2]), v3 = h8f4(vs[i][3]);
        float ax = wt.x*v0.x + wt.y*v1.x + wt.z*v2.x + wt.w*v3.x;
        float ay = wt.x*v0.y + wt.y*v1.y + wt.z*v2.y + wt.w*v3.y;
        float az = wt.x*v0.z + wt.y*v1.z + wt.z*v2.z + wt.w*v3.z;
        float aw = wt.x*v0.w + wt.y*v1.w + wt.z*v2.w + wt.w*v3.w;
        *(float4*)&sB[(uint32_t)col*SLW + cq*4] =
            make_float4(__uint_as_float(f2tf32(ax)), __uint_as_float(f2tf32(ay)),
                        __uint_as_float(f2tf32(az)), __uint_as_float(f2tf32(aw)));
    }
    // issue tap-1 loads (land during first MMA)
#pragma unroll
    for (int i = 0; i < 2; i++) {
        int p = gp0 + i*4 + cs;
        int2 id = sIdx2[p*KK + 1];
        vs[i][0] = gx2[id.x];
        vs[i][1] = gx2[id.x + 8];
        vs[i][2] = gx2[id.y];
        vs[i][3] = gx2[id.y + 8];
    }
    __syncthreads();

    // ---- main loop: 9 taps, deep pipeline
#pragma unroll
    for (int k = 0; k < KK; k++) {
#pragma unroll
        for (int ksl = 0; ksl < 4; ksl++) Acur[ksl] = Anx[ksl];
        if (k + 1 < KK) {
#pragma unroll
            for (int ksl = 0; ksl < 4; ksl++) Anx[ksl] = gw4[((k+1)*4 + ksl)*32];
        }
        // MMA tap k (buf k&1)
        {
            const uint32_t bufb = (uint32_t)(k & 1) * (NCOLS*SLW);
#pragma unroll
            for (int ksl = 0; ksl < 4; ksl++) {
#pragma unroll
                for (int g = 0; g < 4; g++) {
                    uint32_t b0 = sBu[bufb + bOff[g] + ksl*8];
                    uint32_t b1 = sBu[bufb + bOff[g] + ksl*8 + 4];
                    asm volatile(
                        "mma.sync.aligned.m16n8k8.row.col.f32.tf32.tf32.f32 "
                        "{%0,%1,%2,%3}, {%4,%5,%6,%7}, {%8,%9}, {%0,%1,%2,%3};"
                        : "+f"(d[g][0]), "+f"(d[g][1]), "+f"(d[g][2]), "+f"(d[g][3])
                        : "r"(Acur[ksl].x), "r"(Acur[ksl].y),
                          "r"(Acur[ksl].z), "r"(Acur[ksl].w), "r"(b0), "r"(b1));
                }
            }
        }
        if (k + 1 < KK) {
            // combine tap k+1 (loads issued one full stage ago) + store
            float* dstb = sB + (uint32_t)((k + 1) & 1)*(NCOLS*SLW);
#pragma unroll
            for (int i = 0; i < 2; i++) {
                int p   = gp0 + i*4 + cs;
                int col = gcol0 + i*4 + cs;
                float4 wt = sWgt4[p*KK + k + 1];
                float4 v0 = h8f4(vs[i][0]), v1 = h8f4(vs[i][1]);
                float4 v2 = h8f4(vs[i][2]), v3 = h8f4(vs[i][3]);
                float ax = wt.x*v0.x + wt.y*v1.x + wt.z*v2.x + wt.w*v3.x;
                float ay = wt.x*v0.y + wt.y*v1.y + wt.z*v2.y + wt.w*v3.y;
                float az = wt.x*v0.z + wt.y*v1.z + wt.z*v2.z + wt.w*v3.z;
                float aw = wt.x*v0.w + wt.y*v1.w + wt.z*v2.w + wt.w*v3.w;
                *(float4*)&dstb[(uint32_t)col*SLW + cq*4] =
                    make_float4(__uint_as_float(f2tf32(ax)), __uint_as_float(f2tf32(ay)),
                                __uint_as_float(f2tf32(az)), __uint_as_float(f2tf32(aw)));
            }
            // issue tap k+2 loads into freed vs (in flight across sync + next MMA)
            if (k + 2 < KK) {
#pragma unroll
                for (int i = 0; i < 2; i++) {
                    int p = gp0 + i*4 + cs;
                    int2 id = sIdx2[p*KK + k + 2];
                    vs[i][0] = gx2[id.x];
                    vs[i][1] = gx2[id.x + 8];
                    vs[i][2] = gx2[id.y];
                    vs[i][3] = gx2[id.y + 8];
                }
            }
            __syncthreads();
        }
    }

    // ---- epilogue: D row = output channel o, col = (b, pixel)
    {
        int o0 = mw*16 + (lane >> 2);
        float bias0 = sBias[o0];
        float bias1 = sBias[o0 + 8];
#pragma unroll
        for (int g = 0; g < 4; g++) {
            int n  = g*8 + (lane & 3)*2;
            int bb = n >> 4;
            int p  = n & 15;
            float* op = out + ((size_t)(bb*COUT + o0))*OHW + pix0 + p;
            *(float2*)op = make_float2(d[g][0] + bias0, d[g][1] + bias0);
            *(float2*)(op + (size_t)8*OHW) = make_float2(d[g][2] + bias1, d[g][3] + bias1);
        }
    }
}

extern "C" void kernel_launch(void* const* d_in, const int* in_sizes, int n_in,
                              void* d_out, int out_size) {
    const float* x    = (const float*)d_in[0];
    const float* w    = (const float*)d_in[1];
    const float* bias = (const float*)d_in[2];
    const float* smap = (const float*)d_in[3];
    float* out = (float*)d_out;

    transpose_kernel<<<dim3(HWSZ/32, 3), 256>>>(x, w);   // y==2 slice does weights
    mapped_conv_kernel<<<OHW/TPIX, NTHR>>>(bias, smap, out);
}

// round 12
// speedup vs baseline: 1.4571x; 1.4571x over previous
#include <cuda_runtime.h>
#include <cuda_fp16.h>
#include <cstdint>

#define Bb     2
#define CIN    32
#define COUT   64
#define KK     9
#define HH     256
#define WW     512
#define HWSZ   (HH*WW)        // 131072
#define OHW    (HH*WW)        // 131072
#define CK     (CIN*KK)       // 288
#define NKS    (CK/8)         // 36

#define TPIX   16             // pixels per tile
#define NCOLS  32             // gemm N = 16 pix * 2 batch
#define SLW    36             // sB word stride (36%32==4 -> conflict-free frag reads)
#define NTHR   128

// scratch: x transposed to [B, H*W, C] (fp32); weights as fp16-packed tf32 A-fragments
// g_wfrag16[mg(4)][ks(36)][lane(32)][u2] : u2.x = half2(slot0,slot1), u2.y = half2(slot2,slot3)
__device__ __align__(16) float g_xt[(size_t)Bb*HWSZ*CIN];
__device__ __align__(16) uint2 g_wfrag16[4*NKS*32];

__device__ __forceinline__ uint32_t f2tf32(float v) {
    uint32_t u;
    asm("cvt.rna.tf32.f32 %0, %1;" : "=r"(u) : "f"(v));
    return u;
}
__device__ __forceinline__ uint32_t h2u(__half2 h) {
    union { __half2 h; uint32_t u; } c; c.h = h; return c.u;
}
__device__ __forceinline__ float2 u2f2(uint32_t u) {
    union { uint32_t u; __half2 h; } c; c.u = u;
    return __half22float2(c.h);
}

// ------- transpose x: [B,C,HW] -> [B,HW,C], float4 both sides; wt fused on y==2 -------
__global__ void transpose_kernel(const float* __restrict__ x,
                                 const float* __restrict__ w) {
    __shared__ float tile[32][36];
    int b   = blockIdx.y;
    int tid = threadIdx.x;
    if (b == 2) {
        // weights: W[o][c][k] -> fp16-packed A-frag [mg][ks][lane] (2 half2)
        // slot s: o = mg*16 + (lane>>2) + (s&1)*8 ; ck = ks*8 + (lane&3) + (s>>1)*4
        int i = blockIdx.x*256 + tid;        // one uint2 per i
        if (i < 4*NKS*32) {
            int lane = i & 31;
            int ks   = (i >> 5) % NKS;
            int mg   = i / (NKS*32);
            float v[4];
#pragma unroll
            for (int s = 0; s < 4; s++) {
                int o  = mg*16 + (lane >> 2) + (s & 1)*8;
                int ck = ks*8 + (lane & 3) + (s >> 1)*4;
                int c = ck & 31, k = ck >> 5;
                v[s] = w[(o*CIN + c)*KK + k];
            }
            uint2 pk;
            pk.x = h2u(__floats2half2_rn(v[0], v[1]));
            pk.y = h2u(__floats2half2_rn(v[2], v[3]));
            g_wfrag16[i] = pk;
        }
        return;
    }
    int hw0 = blockIdx.x * 32;
    {
        int c = tid >> 3, q = tid & 7;
        float4 v = ((const float4*)x)[(((size_t)(b*CIN + c))*HWSZ + hw0)/4 + q];
        *(float4*)&tile[c][q*4] = v;
    }
    __syncthreads();
    {
        int hw = tid & 31, cq = tid >> 5;
        ((float4*)g_xt)[((size_t)b*HWSZ + hw0 + hw)*8 + cq] =
            make_float4(tile[cq*4+0][hw], tile[cq*4+1][hw],
                        tile[cq*4+2][hw], tile[cq*4+3][hw]);
    }
}

// ---------------- main: deep-pipelined gather + tf32 mma.sync, 4 CTAs/SM ----------------
__global__ void __launch_bounds__(NTHR, 4)
mapped_conv_kernel(const float* __restrict__ bias,
                   const float* __restrict__ smap,
                   float* __restrict__ out)
{
    __shared__ float  sB[2*NCOLS*SLW];     // 2304 fl, double-buffered sampled tile
    __shared__ int4   sIdx4[TPIX*KK];      // 144
    __shared__ float4 sWgt4[TPIX*KK];      // 144
    __shared__ float  sBias[COUT];

    const int tid  = threadIdx.x;
    const int w    = tid >> 5;             // 0..3
    const int lane = tid & 31;
    const int pix0 = blockIdx.x * TPIX;

    if (tid < COUT) sBias[tid] = bias[tid];

    // bilinear tables: task t = p*9+k, 144 tasks
    for (int t = tid; t < TPIX*KK; t += NTHR) {
        int p = t / KK, k = t - p*KK;
        float2 sxy = ((const float2*)smap)[(pix0 + p)*KK + k];
        float bx = floorf(sxy.x), by = floorf(sxy.y);
        float fx = sxy.x - bx,    fy = sxy.y - by;
        int x0 = (int)bx, y0 = (int)by;
        int x0c = min(max(x0, 0), WW-1);
        int x1c = min(x0 + 1, WW-1);
        int y0c = min(max(y0, 0), HH-1);
        int y1c = min(y0 + 1, HH-1);
        sIdx4[t] = make_int4(y0c*WW + x0c, y0c*WW + x1c,
                             y1c*WW + x0c, y1c*WW + x1c);
        sWgt4[t] = make_float4((1.f-fx)*(1.f-fy), fx*(1.f-fy),
                               (1.f-fx)*fy,       fx*fy);
    }

    // gather mapping: warp w -> 8 cols; col = b*16 + p
    const int gb_b  = w >> 1;
    const int gcol0 = w * 8;
    const int gp0   = (w & 1) * 8;
    const int cq    = lane & 7;
    const int cs    = lane >> 3;
    const float4* __restrict__ gxb4 = (const float4*)g_xt + (size_t)gb_b*HWSZ*8 + cq;

    // mma mapping: warp = mw (rows mw*16..+15), all 32 cols
    const int mw = w;
    const uint32_t* sBu = (const uint32_t*)sB;
    uint32_t bOff[4];
#pragma unroll
    for (int g = 0; g < 4; g++)
        bOff[g] = (uint32_t)(g*8 + (lane >> 2))*SLW + (lane & 3);

    const uint2* __restrict__ gw2 = g_wfrag16 + (uint32_t)(mw*NKS)*32 + lane;

    float d[4][4];
#pragma unroll
    for (int g = 0; g < 4; g++)
#pragma unroll
        for (int j = 0; j < 4; j++) d[g][j] = 0.f;

    float4 vs[2][4];     // [col-iter][corner]
    uint2  Acur[4], Anx[4];

    __syncthreads();     // tables ready

    // ---- prologue: gather+store tap 0; issue tap 1 loads; prefetch A(0)
#pragma unroll
    for (int i = 0; i < 2; i++) {
        int p = gp0 + i*4 + cs;
        int4 id = sIdx4[p*KK];
        vs[i][0] = gxb4[(size_t)id.x*8];
        vs[i][1] = gxb4[(size_t)id.y*8];
        vs[i][2] = gxb4[(size_t)id.z*8];
        vs[i][3] = gxb4[(size_t)id.w*8];
    }
#pragma unroll
    for (int ksl = 0; ksl < 4; ksl++) Anx[ksl] = gw2[ksl*32];
#pragma unroll
    for (int i = 0; i < 2; i++) {
        int p   = gp0 + i*4 + cs;
        int col = gcol0 + i*4 + cs;
        float4 wt = sWgt4[p*KK];
        float ax = wt.x*vs[i][0].x + wt.y*vs[i][1].x + wt.z*vs[i][2].x + wt.w*vs[i][3].x;
        float ay = wt.x*vs[i][0].y + wt.y*vs[i][1].y + wt.z*vs[i][2].y + wt.w*vs[i][3].y;
        float az = wt.x*vs[i][0].z + wt.y*vs[i][1].z + wt.z*vs[i][2].z + wt.w*vs[i][3].z;
        float aw = wt.x*vs[i][0].w + wt.y*vs[i][1].w + wt.z*vs[i][2].w + wt.w*vs[i][3].w;
        *(float4*)&sB[(uint32_t)col*SLW + cq*4] =
            make_float4(__uint_as_float(f2tf32(ax)), __uint_as_float(f2tf32(ay)),
                        __uint_as_float(f2tf32(az)), __uint_as_float(f2tf32(aw)));
    }
    // issue tap-1 loads (land during first MMA)
#pragma unroll
    for (int i = 0; i < 2; i++) {
        int p = gp0 + i*4 + cs;
        int4 id = sIdx4[p*KK + 1];
        vs[i][0] = gxb4[(size_t)id.x*8];
        vs[i][1] = gxb4[(size_t)id.y*8];
        vs[i][2] = gxb4[(size_t)id.z*8];
        vs[i][3] = gxb4[(size_t)id.w*8];
    }
    __syncthreads();

    // ---- main loop: 9 taps, deep pipeline
#pragma unroll
    for (int k = 0; k < KK; k++) {
#pragma unroll
        for (int ksl = 0; ksl < 4; ksl++) Acur[ksl] = Anx[ksl];
        if (k + 1 < KK) {
#pragma unroll
            for (int ksl = 0; ksl < 4; ksl++) Anx[ksl] = gw2[((k+1)*4 + ksl)*32];
        }
        // MMA tap k (buf k&1); expand fp16 A-frags to f32 (bit-exact tf32 operands)
        {
            const uint32_t bufb = (uint32_t)(k & 1) * (NCOLS*SLW);
#pragma unroll
            for (int ksl = 0; ksl < 4; ksl++) {
                float2 lo = u2f2(Acur[ksl].x);   // slot0 (A.x), slot1 (A.y)
                float2 hi = u2f2(Acur[ksl].y);   // slot2 (A.z), slot3 (A.w)
                uint32_t Ax = __float_as_uint(lo.x);
                uint32_t Ay = __float_as_uint(lo.y);
                uint32_t Az = __float_as_uint(hi.x);
                uint32_t Aw = __float_as_uint(hi.y);
#pragma unroll
                for (int g = 0; g < 4; g++) {
                    uint32_t b0 = sBu[bufb + bOff[g] + ksl*8];
                    uint32_t b1 = sBu[bufb + bOff[g] + ksl*8 + 4];
                    asm volatile(
                        "mma.sync.aligned.m16n8k8.row.col.f32.tf32.tf32.f32 "
                        "{%0,%1,%2,%3}, {%4,%5,%6,%7}, {%8,%9}, {%0,%1,%2,%3};"
                        : "+f"(d[g][0]), "+f"(d[g][1]), "+f"(d[g][2]), "+f"(d[g][3])
                        : "r"(Ax), "r"(Ay), "r"(Az), "r"(Aw), "r"(b0), "r"(b1));
                }
            }
        }
        if (k + 1 < KK) {
            // combine tap k+1 (loads issued one full stage ago) + store
            float* dstb = sB + (uint32_t)((k + 1) & 1)*(NCOLS*SLW);
#pragma unroll
            for (int i = 0; i < 2; i++) {
                int p   = gp0 + i*4 + cs;
                int col = gcol0 + i*4 + cs;
                float4 wt = sWgt4[p*KK + k + 1];
                float ax = wt.x*vs[i][0].x + wt.y*vs[i][1].x + wt.z*vs[i][2].x + wt.w*vs[i][3].x;
                float ay = wt.x*vs[i][0].y + wt.y*vs[i][1].y + wt.z*vs[i][2].y + wt.w*vs[i][3].y;
                float az = wt.x*vs[i][0].z + wt.y*vs[i][1].z + wt.z*vs[i][2].z + wt.w*vs[i][3].z;
                float aw = wt.x*vs[i][0].w + wt.y*vs[i][1].w + wt.z*vs[i][2].w + wt.w*vs[i][3].w;
                *(float4*)&dstb[(uint32_t)col*SLW + cq*4] =
                    make_float4(__uint_as_float(f2tf32(ax)), __uint_as_float(f2tf32(ay)),
                                __uint_as_float(f2tf32(az)), __uint_as_float(f2tf32(aw)));
            }
            // issue tap k+2 loads into freed vs (in flight across sync + next MMA)
            if (k + 2 < KK) {
#pragma unroll
                for (int i = 0; i < 2; i++) {
                    int p = gp0 + i*4 + cs;
                    int4 id = sIdx4[p*KK + k + 2];
                    vs[i][0] = gxb4[(size_t)id.x*8];
                    vs[i][1] = gxb4[(size_t)id.y*8];
                    vs[i][2] = gxb4[(size_t)id.z*8];
                    vs[i][3] = gxb4[(size_t)id.w*8];
                }
            }
            __syncthreads();
        }
    }

    // ---- epilogue: D row = output channel o, col = (b, pixel)
    {
        int o0 = mw*16 + (lane >> 2);
        float bias0 = sBias[o0];
        float bias1 = sBias[o0 + 8];
#pragma unroll
        for (int g = 0; g < 4; g++) {
            int n  = g*8 + (lane & 3)*2;
            int bb = n >> 4;
            int p  = n & 15;
            float* op = out + ((size_t)(bb*COUT + o0))*OHW + pix0 + p;
            *(float2*)op = make_float2(d[g][0] + bias0, d[g][1] + bias0);
            *(float2*)(op + (size_t)8*OHW) = make_float2(d[g][2] + bias1, d[g][3] + bias1);
        }
    }
}

extern "C" void kernel_launch(void* const* d_in, const int* in_sizes, int n_in,
                              void* d_out, int out_size) {
    const float* x    = (const float*)d_in[0];
    const float* w    = (const float*)d_in[1];
    const float* bias = (const float*)d_in[2];
    const float* smap = (const float*)d_in[3];
    float* out = (float*)d_out;

    transpose_kernel<<<dim3(HWSZ/32, 3), 256>>>(x, w);   // y==2 slice does weights
    mapped_conv_kernel<<<OHW/TPIX, NTHR>>>(bias, smap, out);
}

// round 13
// speedup vs baseline: 1.6851x; 1.1565x over previous
#include <cuda_runtime.h>
#include <cuda_fp16.h>
#include <cstdint>

#define Bb     2
#define CIN    32
#define COUT   64
#define KK     9
#define HH     256
#define WW     512
#define HWSZ   (HH*WW)        // 131072
#define OHW    (HH*WW)        // 131072
#define CK     (CIN*KK)       // 288
#define NKS16  (CK/16)        // 18 k16-steps

#define TPIX   16             // pixels per tile
#define NCOLS  32             // gemm N = 16 pix * 2 batch
#define SLH    20             // sB half2-word stride per col (20*l2 mod 32 is a permutation)
#define NTHR   128

// scratch: x transposed to [B, H*W, C] (fp32); weights as fp16 m16n8k16 A-fragments
// g_wfragA[mg(4)][ks(18)][lane(32)] = uint4 (a0,a1,a2,a3 half2)
__device__ __align__(16) float g_xt[(size_t)Bb*HWSZ*CIN];
__device__ __align__(16) uint4 g_wfragA[4*NKS16*32];

__device__ __forceinline__ uint32_t h2u(__half2 h) {
    union { __half2 h; uint32_t u; } c; c.h = h; return c.u;
}

// ------- transpose x: [B,C,HW] -> [B,HW,C], float4 both sides; wt fused on y==2 -------
__global__ void transpose_kernel(const float* __restrict__ x,
                                 const float* __restrict__ w) {
    __shared__ float tile[32][36];
    int b   = blockIdx.y;
    int tid = threadIdx.x;
    if (b == 2) {
        // weights: W[o][c][k] -> fp16 m16n8k16 A-frag [mg][ks][lane] = uint4
        // a0: row l2,   ck ks*16 + l1*2 +{0,1} ; a1: row l2+8 ; a2/a3: ck +8
        int i = blockIdx.x*256 + tid;
        if (i < 4*NKS16*32) {
            int lane = i & 31;
            int ks   = (i >> 5) % NKS16;
            int mg   = i / (NKS16*32);
            int l2 = lane >> 2, l1 = lane & 3;
            float v[8];
#pragma unroll
            for (int r = 0; r < 2; r++)          // row group: +0 / +8
#pragma unroll
            for (int kk2 = 0; kk2 < 2; kk2++)    // ck group: +0 / +8
#pragma unroll
            for (int e = 0; e < 2; e++) {
                int o  = mg*16 + l2 + r*8;
                int ck = ks*16 + l1*2 + kk2*8 + e;
                int c = ck & 31, k = ck >> 5;
                v[r + kk2*4 + e*2] = w[(o*CIN + c)*KK + k];
            }
            uint4 pk;
            pk.x = h2u(__floats2half2_rn(v[0], v[2]));   // a0: row+0, ck, ck+1
            pk.y = h2u(__floats2half2_rn(v[1], v[3]));   // a1: row+8
            pk.z = h2u(__floats2half2_rn(v[4], v[6]));   // a2: row+0, ck+8, ck+9
            pk.w = h2u(__floats2half2_rn(v[5], v[7]));   // a3: row+8
            g_wfragA[i] = pk;
        }
        return;
    }
    int hw0 = blockIdx.x * 32;
    {
        int c = tid >> 3, q = tid & 7;
        float4 v = ((const float4*)x)[(((size_t)(b*CIN + c))*HWSZ + hw0)/4 + q];
        *(float4*)&tile[c][q*4] = v;
    }
    __syncthreads();
    {
        int hw = tid & 31, cq = tid >> 5;
        ((float4*)g_xt)[((size_t)b*HWSZ + hw0 + hw)*8 + cq] =
            make_float4(tile[cq*4+0][hw], tile[cq*4+1][hw],
                        tile[cq*4+2][hw], tile[cq*4+3][hw]);
    }
}

// ---------------- main: deep-pipelined fp32 gather + f16 mma.sync, 4 CTAs/SM ----------------
__global__ void __launch_bounds__(NTHR, 4)
mapped_conv_kernel(const float* __restrict__ bias,
                   const float* __restrict__ smap,
                   float* __restrict__ out)
{
    __shared__ uint32_t sB[2*NCOLS*SLH];   // 1280 u32, double-buffered half2 sampled tile
    __shared__ int4   sIdx4[TPIX*KK];      // 144
    __shared__ float4 sWgt4[TPIX*KK];      // 144
    __shared__ float  sBias[COUT];

    const int tid  = threadIdx.x;
    const int w    = tid >> 5;             // 0..3
    const int lane = tid & 31;
    const int pix0 = blockIdx.x * TPIX;

    if (tid < COUT) sBias[tid] = bias[tid];

    // bilinear tables: task t = p*9+k, 144 tasks
    for (int t = tid; t < TPIX*KK; t += NTHR) {
        int p = t / KK, k = t - p*KK;
        float2 sxy = ((const float2*)smap)[(pix0 + p)*KK + k];
        float bx = floorf(sxy.x), by = floorf(sxy.y);
        float fx = sxy.x - bx,    fy = sxy.y - by;
        int x0 = (int)bx, y0 = (int)by;
        int x0c = min(max(x0, 0), WW-1);
        int x1c = min(x0 + 1, WW-1);
        int y0c = min(max(y0, 0), HH-1);
        int y1c = min(y0 + 1, HH-1);
        sIdx4[t] = make_int4(y0c*WW + x0c, y0c*WW + x1c,
                             y1c*WW + x0c, y1c*WW + x1c);
        sWgt4[t] = make_float4((1.f-fx)*(1.f-fy), fx*(1.f-fy),
                               (1.f-fx)*fy,       fx*fy);
    }

    // gather mapping: warp w -> 8 cols; col = b*16 + p ; lane = cq(8) x cs(4)
    const int gb_b  = w >> 1;
    const int gcol0 = w * 8;
    const int gp0   = (w & 1) * 8;
    const int cq    = lane & 7;
    const int cs    = lane >> 3;
    const float4* __restrict__ gxb4 = (const float4*)g_xt + (size_t)gb_b*HWSZ*8 + cq;

    // mma mapping: warp = mw (rows mw*16..+15), all 32 cols
    const int mw = w;
    uint32_t bOff[4];
#pragma unroll
    for (int g = 0; g < 4; g++)
        bOff[g] = (uint32_t)(g*8 + (lane >> 2))*SLH + (lane & 3);

    const uint4* __restrict__ gwA = g_wfragA + (uint32_t)(mw*NKS16)*32 + lane;

    float d[4][4];
#pragma unroll
    for (int g = 0; g < 4; g++)
#pragma unroll
        for (int j = 0; j < 4; j++) d[g][j] = 0.f;

    float4 vs[2][4];     // [col-iter][corner]
    uint4  Acur[2], Anx[2];

    __syncthreads();     // tables ready

    // ---- prologue: gather+store tap 0; issue tap 1 loads; prefetch A(0)
#pragma unroll
    for (int i = 0; i < 2; i++) {
        int p = gp0 + i*4 + cs;
        int4 id = sIdx4[p*KK];
        vs[i][0] = gxb4[(size_t)id.x*8];
        vs[i][1] = gxb4[(size_t)id.y*8];
        vs[i][2] = gxb4[(size_t)id.z*8];
        vs[i][3] = gxb4[(size_t)id.w*8];
    }
#pragma unroll
    for (int h = 0; h < 2; h++) Anx[h] = gwA[h*32];
#pragma unroll
    for (int i = 0; i < 2; i++) {
        int p   = gp0 + i*4 + cs;
        int col = gcol0 + i*4 + cs;
        float4 wt = sWgt4[p*KK];
        float ax = wt.x*vs[i][0].x + wt.y*vs[i][1].x + wt.z*vs[i][2].x + wt.w*vs[i][3].x;
        float ay = wt.x*vs[i][0].y + wt.y*vs[i][1].y + wt.z*vs[i][2].y + wt.w*vs[i][3].y;
        float az = wt.x*vs[i][0].z + wt.y*vs[i][1].z + wt.z*vs[i][2].z + wt.w*vs[i][3].z;
        float aw = wt.x*vs[i][0].w + wt.y*vs[i][1].w + wt.z*vs[i][2].w + wt.w*vs[i][3].w;
        sB[(uint32_t)col*SLH + cq*2    ] = h2u(__floats2half2_rn(ax, ay));
        sB[(uint32_t)col*SLH + cq*2 + 1] = h2u(__floats2half2_rn(az, aw));
    }
    // issue tap-1 loads (land during first MMA)
#pragma unroll
    for (int i = 0; i < 2; i++) {
        int p = gp0 + i*4 + cs;
        int4 id = sIdx4[p*KK + 1];
        vs[i][0] = gxb4[(size_t)id.x*8];
        vs[i][1] = gxb4[(size_t)id.y*8];
        vs[i][2] = gxb4[(size_t)id.z*8];
        vs[i][3] = gxb4[(size_t)id.w*8];
    }
    __syncthreads();

    // ---- main loop: 9 taps, deep pipeline
#pragma unroll
    for (int k = 0; k < KK; k++) {
#pragma unroll
        for (int h = 0; h < 2; h++) Acur[h] = Anx[h];
        if (k + 1 < KK) {
#pragma unroll
            for (int h = 0; h < 2; h++) Anx[h] = gwA[((k+1)*2 + h)*32];
        }
        // MMA tap k (buf k&1): 2 k16-steps x 4 n-groups
        {
            const uint32_t bufb = (uint32_t)(k & 1) * (NCOLS*SLH);
#pragma unroll
            for (int h = 0; h < 2; h++) {
#pragma unroll
                for (int g = 0; g < 4; g++) {
                    uint32_t b0 = sB[bufb + bOff[g] + h*8];
                    uint32_t b1 = sB[bufb + bOff[g] + h*8 + 4];
                    asm volatile(
                        "mma.sync.aligned.m16n8k16.row.col.f32.f16.f16.f32 "
                        "{%0,%1,%2,%3}, {%4,%5,%6,%7}, {%8,%9}, {%0,%1,%2,%3};"
                        : "+f"(d[g][0]), "+f"(d[g][1]), "+f"(d[g][2]), "+f"(d[g][3])
                        : "r"(Acur[h].x), "r"(Acur[h].y),
                          "r"(Acur[h].z), "r"(Acur[h].w), "r"(b0), "r"(b1));
                }
            }
        }
        if (k + 1 < KK) {
            // combine tap k+1 (loads issued one full stage ago) + store
            uint32_t* dstb = sB + (uint32_t)((k + 1) & 1)*(NCOLS*SLH);
#pragma unroll
            for (int i = 0; i < 2; i++) {
                int p   = gp0 + i*4 + cs;
                int col = gcol0 + i*4 + cs;
                float4 wt = sWgt4[p*KK + k + 1];
                float ax = wt.x*vs[i][0].x + wt.y*vs[i][1].x + wt.z*vs[i][2].x + wt.w*vs[i][3].x;
                float ay = wt.x*vs[i][0].y + wt.y*vs[i][1].y + wt.z*vs[i][2].y + wt.w*vs[i][3].y;
                float az = wt.x*vs[i][0].z + wt.y*vs[i][1].z + wt.z*vs[i][2].z + wt.w*vs[i][3].z;
                float aw = wt.x*vs[i][0].w + wt.y*vs[i][1].w + wt.z*vs[i][2].w + wt.w*vs[i][3].w;
                dstb[(uint32_t)col*SLH + cq*2    ] = h2u(__floats2half2_rn(ax, ay));
                dstb[(uint32_t)col*SLH + cq*2 + 1] = h2u(__floats2half2_rn(az, aw));
            }
            // issue tap k+2 loads into freed vs (in flight across sync + next MMA)
            if (k + 2 < KK) {
#pragma unroll
                for (int i = 0; i < 2; i++) {
                    int p = gp0 + i*4 + cs;
                    int4 id = sIdx4[p*KK + k + 2];
                    vs[i][0] = gxb4[(size_t)id.x*8];
                    vs[i][1] = gxb4[(size_t)id.y*8];
                    vs[i][2] = gxb4[(size_t)id.z*8];
                    vs[i][3] = gxb4[(size_t)id.w*8];
                }
            }
            __syncthreads();
        }
    }

    // ---- epilogue: D row = output channel o, col = (b, pixel)
    {
        int o0 = mw*16 + (lane >> 2);
        float bias0 = sBias[o0];
        float bias1 = sBias[o0 + 8];
#pragma unroll
        for (int g = 0; g < 4; g++) {
            int n  = g*8 + (lane & 3)*2;
            int bb = n >> 4;
            int p  = n & 15;
            float* op = out + ((size_t)(bb*COUT + o0))*OHW + pix0 + p;
            *(float2*)op = make_float2(d[g][0] + bias0, d[g][1] + bias0);
            *(float2*)(op + (size_t)8*OHW) = make_float2(d[g][2] + bias1, d[g][3] + bias1);
        }
    }
}

extern "C" void kernel_launch(void* const* d_in, const int* in_sizes, int n_in,
                              void* d_out, int out_size) {
    const float* x    = (const float*)d_in[0];
    const float* w    = (const float*)d_in[1];
    const float* bias = (const float*)d_in[2];
    const float* smap = (const float*)d_in[3];
    float* out = (float*)d_out;

    transpose_kernel<<<dim3(HWSZ/32, 3), 256>>>(x, w);   // y==2 slice does weights
    mapped_conv_kernel<<<OHW/TPIX, NTHR>>>(bias, smap, out);
}

// round 14
// speedup vs baseline: 1.9531x; 1.1590x over previous
#include <cuda_runtime.h>
#include <cuda_fp16.h>
#include <cstdint>

#define Bb     2
#define CIN    32
#define COUT   64
#define KK     9
#define HH     256
#define WW     512
#define HWSZ   (HH*WW)        // 131072
#define OHW    (HH*WW)        // 131072
#define CK     (CIN*KK)       // 288
#define NKS16  (CK/16)        // 18 k16-steps

#define TPIX   16             // pixels per tile
#define NCOLS  32             // gemm N = 16 pix * 2 batch
#define SLH    20             // sB half2-word stride per col (conflict-free frag reads)
#define NTHR   128

// scratch: x transposed to fp16 [B, H*W, C]; weights as fp16 m16n8k16 A-fragments
__device__ __align__(16) uint2 g_xth[(size_t)Bb*HWSZ*8 + 16];   // uint2 = 4 halves
__device__ __align__(16) uint4 g_wfragA[4*NKS16*32];

__device__ __forceinline__ uint32_t h2u(__half2 h) {
    union { __half2 h; uint32_t u; } c; c.h = h; return c.u;
}
__device__ __forceinline__ __half2 u2h(uint32_t u) {
    union { uint32_t u; __half2 h; } c; c.u = u; return c.h;
}

// ------- transpose x: [B,C,HW] -> fp16 [B,HW,C]; wt fragment bake on y==2 -------
__global__ void transpose_kernel(const float* __restrict__ x,
                                 const float* __restrict__ w) {
    __shared__ float tile[32][36];
    int b   = blockIdx.y;
    int tid = threadIdx.x;
    if (b == 2) {
        // weights: W[o][c][k] -> fp16 m16n8k16 A-frag [mg][ks][lane] = uint4
        int i = blockIdx.x*256 + tid;
        if (i < 4*NKS16*32) {
            int lane = i & 31;
            int ks   = (i >> 5) % NKS16;
            int mg   = i / (NKS16*32);
            int l2 = lane >> 2, l1 = lane & 3;
            float v[8];
#pragma unroll
            for (int r = 0; r < 2; r++)
#pragma unroll
            for (int kk2 = 0; kk2 < 2; kk2++)
#pragma unroll
            for (int e = 0; e < 2; e++) {
                int o  = mg*16 + l2 + r*8;
                int ck = ks*16 + l1*2 + kk2*8 + e;
                int c = ck & 31, k = ck >> 5;
                v[r + kk2*4 + e*2] = w[(o*CIN + c)*KK + k];
            }
            uint4 pk;
            pk.x = h2u(__floats2half2_rn(v[0], v[2]));
            pk.y = h2u(__floats2half2_rn(v[1], v[3]));
            pk.z = h2u(__floats2half2_rn(v[4], v[6]));
            pk.w = h2u(__floats2half2_rn(v[5], v[7]));
            g_wfragA[i] = pk;
        }
        return;
    }
    int hw0 = blockIdx.x * 32;
    {
        int c = tid >> 3, q = tid & 7;
        float4 v = ((const float4*)x)[(((size_t)(b*CIN + c))*HWSZ + hw0)/4 + q];
        *(float4*)&tile[c][q*4] = v;
    }
    __syncthreads();
    {
        int hw = tid & 31, cg = tid >> 5;    // cg 0..7 -> 4-channel group
        uint2 pk;
        pk.x = h2u(__floats2half2_rn(tile[cg*4+0][hw], tile[cg*4+1][hw]));
        pk.y = h2u(__floats2half2_rn(tile[cg*4+2][hw], tile[cg*4+3][hw]));
        g_xth[((size_t)b*HWSZ + hw0 + hw)*8 + cg] = pk;
    }
}

// ---------------- main: fp16 gather + half2 combine + f16 mma.sync, 6 CTAs/SM ----------------
__global__ void __launch_bounds__(NTHR, 6)
mapped_conv_kernel(const float* __restrict__ bias,
                   const float* __restrict__ smap,
                   float* __restrict__ out)
{
    __shared__ uint32_t sB[2*NCOLS*SLH];   // 1280 u32, double-buffered half2 sampled tile
    __shared__ int4   sIdx4[TPIX*KK];      // 144
    __shared__ uint4  sWgtH[TPIX*KK];      // 144: 4 duplicated-half2 bilinear weights
    __shared__ float  sBias[COUT];

    const int tid  = threadIdx.x;
    const int w    = tid >> 5;             // 0..3
    const int lane = tid & 31;
    const int pix0 = blockIdx.x * TPIX;

    if (tid < COUT) sBias[tid] = bias[tid];

    // bilinear tables: task t = p*9+k, 144 tasks
    for (int t = tid; t < TPIX*KK; t += NTHR) {
        int p = t / KK, k = t - p*KK;
        float2 sxy = ((const float2*)smap)[(pix0 + p)*KK + k];
        float bx = floorf(sxy.x), by = floorf(sxy.y);
        float fx = sxy.x - bx,    fy = sxy.y - by;
        int x0 = (int)bx, y0 = (int)by;
        int x0c = min(max(x0, 0), WW-1);
        int x1c = min(x0 + 1, WW-1);
        int y0c = min(max(y0, 0), HH-1);
        int y1c = min(y0 + 1, HH-1);
        sIdx4[t] = make_int4(y0c*WW + x0c, y0c*WW + x1c,
                             y1c*WW + x0c, y1c*WW + x1c);
        uint4 wh;
        wh.x = h2u(__float2half2_rn((1.f-fx)*(1.f-fy)));
        wh.y = h2u(__float2half2_rn(fx*(1.f-fy)));
        wh.z = h2u(__float2half2_rn((1.f-fx)*fy));
        wh.w = h2u(__float2half2_rn(fx*fy));
        sWgtH[t] = wh;
    }

    // gather mapping: warp w -> 8 cols; col = b*16 + p ; lane = cq(8) x cs(4)
    const int gb_b  = w >> 1;
    const int gcol0 = w * 8;
    const int gp0   = (w & 1) * 8;
    const int cq    = lane & 7;
    const int cs    = lane >> 3;
    const uint2* __restrict__ gxh = g_xth + (size_t)gb_b*HWSZ*8 + cq;

    // mma mapping: warp = mw (rows mw*16..+15), all 32 cols
    const int mw = w;
    uint32_t bOff[4];
#pragma unroll
    for (int g = 0; g < 4; g++)
        bOff[g] = (uint32_t)(g*8 + (lane >> 2))*SLH + (lane & 3);

    const uint4* __restrict__ gwA = g_wfragA + (uint32_t)(mw*NKS16)*32 + lane;

    float d[4][4];
#pragma unroll
    for (int g = 0; g < 4; g++)
#pragma unroll
        for (int j = 0; j < 4; j++) d[g][j] = 0.f;

    uint2 vs[2][4];      // [col-iter][corner], 4 halves each

    __syncthreads();     // tables ready

    // ---- prologue: gather+store tap 0; issue tap 1 loads
#pragma unroll
    for (int i = 0; i < 2; i++) {
        int p = gp0 + i*4 + cs;
        int4 id = sIdx4[p*KK];
        vs[i][0] = gxh[(size_t)id.x*8];
        vs[i][1] = gxh[(size_t)id.y*8];
        vs[i][2] = gxh[(size_t)id.z*8];
        vs[i][3] = gxh[(size_t)id.w*8];
    }
#pragma unroll
    for (int i = 0; i < 2; i++) {
        int p   = gp0 + i*4 + cs;
        int col = gcol0 + i*4 + cs;
        uint4 wh = sWgtH[p*KK];
        __half2 a0 = __hmul2(u2h(wh.x), u2h(vs[i][0].x));
        a0 = __hfma2(u2h(wh.y), u2h(vs[i][1].x), a0);
        a0 = __hfma2(u2h(wh.z), u2h(vs[i][2].x), a0);
        a0 = __hfma2(u2h(wh.w), u2h(vs[i][3].x), a0);
        __half2 a1 = __hmul2(u2h(wh.x), u2h(vs[i][0].y));
        a1 = __hfma2(u2h(wh.y), u2h(vs[i][1].y), a1);
        a1 = __hfma2(u2h(wh.z), u2h(vs[i][2].y), a1);
        a1 = __hfma2(u2h(wh.w), u2h(vs[i][3].y), a1);
        sB[(uint32_t)col*SLH + cq*2    ] = h2u(a0);
        sB[(uint32_t)col*SLH + cq*2 + 1] = h2u(a1);
    }
#pragma unroll
    for (int i = 0; i < 2; i++) {
        int p = gp0 + i*4 + cs;
        int4 id = sIdx4[p*KK + 1];
        vs[i][0] = gxh[(size_t)id.x*8];
        vs[i][1] = gxh[(size_t)id.y*8];
        vs[i][2] = gxh[(size_t)id.z*8];
        vs[i][3] = gxh[(size_t)id.w*8];
    }
    __syncthreads();

    // ---- main loop: 9 taps, deep pipeline
#pragma unroll
    for (int k = 0; k < KK; k++) {
        // MMA tap k (buf k&1): A loaded inline (L1-hot), 2 k16-steps x 4 n-groups
        {
            const uint32_t bufb = (uint32_t)(k & 1) * (NCOLS*SLH);
#pragma unroll
            for (int h = 0; h < 2; h++) {
                uint4 A = gwA[(k*2 + h)*32];
#pragma unroll
                for (int g = 0; g < 4; g++) {
                    uint32_t b0 = sB[bufb + bOff[g] + h*8];
                    uint32_t b1 = sB[bufb + bOff[g] + h*8 + 4];
                    asm volatile(
                        "mma.sync.aligned.m16n8k16.row.col.f32.f16.f16.f32 "
                        "{%0,%1,%2,%3}, {%4,%5,%6,%7}, {%8,%9}, {%0,%1,%2,%3};"
                        : "+f"(d[g][0]), "+f"(d[g][1]), "+f"(d[g][2]), "+f"(d[g][3])
                        : "r"(A.x), "r"(A.y), "r"(A.z), "r"(A.w), "r"(b0), "r"(b1));
                }
            }
        }
        if (k + 1 < KK) {
            // combine tap k+1 (loads issued one full stage ago) + store
            uint32_t* dstb = sB + (uint32_t)((k + 1) & 1)*(NCOLS*SLH);
#pragma unroll
            for (int i = 0; i < 2; i++) {
                int p   = gp0 + i*4 + cs;
                int col = gcol0 + i*4 + cs;
                uint4 wh = sWgtH[p*KK + k + 1];
                __half2 a0 = __hmul2(u2h(wh.x), u2h(vs[i][0].x));
                a0 = __hfma2(u2h(wh.y), u2h(vs[i][1].x), a0);
                a0 = __hfma2(u2h(wh.z), u2h(vs[i][2].x), a0);
                a0 = __hfma2(u2h(wh.w), u2h(vs[i][3].x), a0);
                __half2 a1 = __hmul2(u2h(wh.x), u2h(vs[i][0].y));
                a1 = __hfma2(u2h(wh.y), u2h(vs[i][1].y), a1);
                a1 = __hfma2(u2h(wh.z), u2h(vs[i][2].y), a1);
                a1 = __hfma2(u2h(wh.w), u2h(vs[i][3].y), a1);
                dstb[(uint32_t)col*SLH + cq*2    ] = h2u(a0);
                dstb[(uint32_t)col*SLH + cq*2 + 1] = h2u(a1);
            }
            // issue tap k+2 loads into freed vs
            if (k + 2 < KK) {
#pragma unroll
                for (int i = 0; i < 2; i++) {
                    int p = gp0 + i*4 + cs;
                    int4 id = sIdx4[p*KK + k + 2];
                    vs[i][0] = gxh[(size_t)id.x*8];
                    vs[i][1] = gxh[(size_t)id.y*8];
                    vs[i][2] = gxh[(size_t)id.z*8];
                    vs[i][3] = gxh[(size_t)id.w*8];
                }
            }
            __syncthreads();
        }
    }

    // ---- epilogue: D row = output channel o, col = (b, pixel)
    {
        int o0 = mw*16 + (lane >> 2);
        float bias0 = sBias[o0];
        float bias1 = sBias[o0 + 8];
#pragma unroll
        for (int g = 0; g < 4; g++) {
            int n  = g*8 + (lane & 3)*2;
            int bb = n >> 4;
            int p  = n & 15;
            float* op = out + ((size_t)(bb*COUT + o0))*OHW + pix0 + p;
            *(float2*)op = make_float2(d[g][0] + bias0, d[g][1] + bias0);
            *(float2*)(op + (size_t)8*OHW) = make_float2(d[g][2] + bias1, d[g][3] + bias1);
        }
    }
}

extern "C" void kernel_launch(void* const* d_in, const int* in_sizes, int n_in,
                              void* d_out, int out_size) {
    const float* x    = (const float*)d_in[0];
    const float* w    = (const float*)d_in[1];
    const float* bias = (const float*)d_in[2];
    const float* smap = (const float*)d_in[3];
    float* out = (float*)d_out;

    transpose_kernel<<<dim3(HWSZ/32, 3), 256>>>(x, w);   // y==2 slice does weights
    mapped_conv_kernel<<<OHW/TPIX, NTHR>>>(bias, smap, out);
}

// round 16
// speedup vs baseline: 2.1436x; 1.0976x over previous
#include <cuda_runtime.h>
#include <cuda_fp16.h>
#include <cstdint>

#define Bb     2
#define CIN    32
#define COUT   64
#define KK     9
#define HH     256
#define WW     512
#define HWSZ   (HH*WW)        // 131072
#define OHW    (HH*WW)        // 131072
#define CK     (CIN*KK)       // 288
#define NKS16  (CK/16)        // 18 k16-steps
#define PBE    (Bb*HWSZ/2)    // 131072 pair-entries per parity block

#define TPIX   16             // pixels per tile
#define NCOLS  32             // gemm N = 16 pix * 2 batch
#define SLH    20             // sB half2-word stride per col (conflict-free frag reads)
#define NTHR   128

// scratch: x as x-pair-interleaved fp16 [parity][B][H][W/2] (128B entries:
//   entry half2[c] = (v[x0][c], v[x0+1][c]) ), weights as fp16 m16n8k16 A-fragments
__device__ __align__(16) uint4 g_xp[2*PBE*8];
__device__ __align__(16) uint4 g_wfragA[4*NKS16*32];

__device__ __forceinline__ uint32_t h2u(__half2 h) {
    union { __half2 h; uint32_t u; } c; c.h = h; return c.u;
}
__device__ __forceinline__ __half2 u2h(uint32_t u) {
    union { uint32_t u; __half2 h; } c; c.u = u; return c.h;
}

// ------- transpose x -> pair-interleaved fp16; wt fragment bake on y==2 -------
__global__ void transpose_kernel(const float* __restrict__ x,
                                 const float* __restrict__ w) {
    __shared__ float tile[32][36];     // [c][hw 0..32]
    int b   = blockIdx.y;
    int tid = threadIdx.x;
    if (b == 2) {
        int i = blockIdx.x*256 + tid;
        if (i < 4*NKS16*32) {
            int lane = i & 31;
            int ks   = (i >> 5) % NKS16;
            int mg   = i / (NKS16*32);
            int l2 = lane >> 2, l1 = lane & 3;
            float v[8];
#pragma unroll
            for (int r = 0; r < 2; r++)
#pragma unroll
            for (int kk2 = 0; kk2 < 2; kk2++)
#pragma unroll
            for (int e = 0; e < 2; e++) {
                int o  = mg*16 + l2 + r*8;
                int ck = ks*16 + l1*2 + kk2*8 + e;
                int c = ck & 31, k = ck >> 5;
                v[r + kk2*4 + e*2] = w[(o*CIN + c)*KK + k];
            }
            uint4 pk;
            pk.x = h2u(__floats2half2_rn(v[0], v[2]));
            pk.y = h2u(__floats2half2_rn(v[1], v[3]));
            pk.z = h2u(__floats2half2_rn(v[4], v[6]));
            pk.w = h2u(__floats2half2_rn(v[5], v[7]));
            g_wfragA[i] = pk;
        }
        return;
    }
    int hw0 = blockIdx.x * 32;
    {
        int c = tid >> 3, q = tid & 7;
        float4 v = ((const float4*)x)[(((size_t)(b*CIN + c))*HWSZ + hw0)/4 + q];
        *(float4*)&tile[c][q*4] = v;
        if (q == 0) {   // 33rd column (clamped at plane end; used only w/ weight 0)
            size_t src = (size_t)(b*CIN + c)*HWSZ + hw0 + 32;
            if (hw0 + 32 >= HWSZ) src = (size_t)(b*CIN + c)*HWSZ + HWSZ - 1;
            tile[c][32] = x[src];
        }
    }
    __syncthreads();
    {
        int par = tid >> 7, j = (tid >> 3) & 15, q = tid & 7;
        int x0l = 2*j + par;
        int c0  = q*4;
        uint4 pk;
        pk.x = h2u(__floats2half2_rn(tile[c0+0][x0l], tile[c0+0][x0l+1]));
        pk.y = h2u(__floats2half2_rn(tile[c0+1][x0l], tile[c0+1][x0l+1]));
        pk.z = h2u(__floats2half2_rn(tile[c0+2][x0l], tile[c0+2][x0l+1]));
        pk.w = h2u(__floats2half2_rn(tile[c0+3][x0l], tile[c0+3][x0l+1]));
        size_t e = (size_t)par*PBE + (((size_t)b*HWSZ + hw0 + x0l) >> 1);
        g_xp[e*8 + q] = pk;
    }
}

// ---------------- main: paired fp16 gather + half2 combine + f16 mma.sync ----------------
__global__ void __launch_bounds__(NTHR, 6)
mapped_conv_kernel(const float* __restrict__ bias,
                   const float* __restrict__ smap,
                   float* __restrict__ out)
{
    __shared__ uint32_t sB[2*NCOLS*SLH];   // 1280 u32, double-buffered half2 sampled tile
    __shared__ int2   sIdx2[TPIX*KK];      // 144: pair-entry indices (y0,x0pair),(y1,x0pair)
    __shared__ uint4  sWgtH[TPIX*KK];      // 144: 4 duplicated-half2 bilinear weights
    __shared__ float  sBias[COUT];

    const int tid  = threadIdx.x;
    const int w    = tid >> 5;             // 0..3
    const int lane = tid & 31;
    const int pix0 = blockIdx.x * TPIX;

    if (tid < COUT) sBias[tid] = bias[tid];

    // bilinear tables: task t = p*9+k, 144 tasks
    for (int t = tid; t < TPIX*KK; t += NTHR) {
        int p = t / KK, k = t - p*KK;
        float2 sxy = ((const float2*)smap)[(pix0 + p)*KK + k];
        float bx = floorf(sxy.x), by = floorf(sxy.y);
        float fx = sxy.x - bx,    fy = sxy.y - by;
        int x0 = (int)bx, y0 = (int)by;
        int x0c = min(max(x0, 0), WW-1);   // pair (x0c, x0c+1); x0c==511 -> w01==0
        int y0c = min(max(y0, 0), HH-1);
        int y1c = min(y0 + 1, HH-1);
        int par = x0c & 1;
        sIdx2[t] = make_int2(par*PBE + ((y0c*WW + x0c) >> 1),
                             par*PBE + ((y1c*WW + x0c) >> 1));
        uint4 wh;
        wh.x = h2u(__float2half2_rn((1.f-fx)*(1.f-fy)));
        wh.y = h2u(__float2half2_rn(fx*(1.f-fy)));
        wh.z = h2u(__float2half2_rn((1.f-fx)*fy));
        wh.w = h2u(__float2half2_rn(fx*fy));
        sWgtH[t] = wh;
    }

    // gather mapping: warp w -> 8 cols; col = b*16 + p ; lane = q(8 ch-quads) x cs(4)
    const int gb_b  = w >> 1;
    const int gcol0 = w * 8;
    const int gp0   = (w & 1) * 8;
    const int q     = lane & 7;
    const int cs    = lane >> 3;
    const uint4* __restrict__ gxp = g_xp + (size_t)gb_b*(HWSZ/2)*8 + q;

    // mma mapping: warp = mw (rows mw*16..+15), all 32 cols
    const int mw = w;
    uint32_t bOff[4];
#pragma unroll
    for (int g = 0; g < 4; g++)
        bOff[g] = (uint32_t)(g*8 + (lane >> 2))*SLH + (lane & 3);

    const uint4* __restrict__ gwA = g_wfragA + (uint32_t)(mw*NKS16)*32 + lane;

    float d[4][4];
#pragma unroll
    for (int g = 0; g < 4; g++)
#pragma unroll
        for (int j = 0; j < 4; j++) d[g][j] = 0.f;

    uint4 vs[2][2];      // [col-iter][y-corner]: 4 half2 = 4 ch x (x0,x1)

    __syncthreads();     // tables ready

#define COMBINE_STORE(DST, VI, WIDX)                                           \
    {                                                                          \
        uint4 wh = sWgtH[WIDX];                                                \
        uint4 vA = vs[VI][0], vB = vs[VI][1];                                  \
        __half2 a01l = __lows2half2(u2h(vA.x), u2h(vA.y));                     \
        __half2 a01h = __highs2half2(u2h(vA.x), u2h(vA.y));                    \
        __half2 a23l = __lows2half2(u2h(vA.z), u2h(vA.w));                     \
        __half2 a23h = __highs2half2(u2h(vA.z), u2h(vA.w));                    \
        __half2 b01l = __lows2half2(u2h(vB.x), u2h(vB.y));                     \
        __half2 b01h = __highs2half2(u2h(vB.x), u2h(vB.y));                    \
        __half2 b23l = __lows2half2(u2h(vB.z), u2h(vB.w));                     \
        __half2 b23h = __highs2half2(u2h(vB.z), u2h(vB.w));                    \
        __half2 r01 = __hmul2(u2h(wh.x), a01l);                                \
        r01 = __hfma2(u2h(wh.y), a01h, r01);                                   \
        r01 = __hfma2(u2h(wh.z), b01l, r01);                                   \
        r01 = __hfma2(u2h(wh.w), b01h, r01);                                   \
        __half2 r23 = __hmul2(u2h(wh.x), a23l);                                \
        r23 = __hfma2(u2h(wh.y), a23h, r23);                                   \
        r23 = __hfma2(u2h(wh.z), b23l, r23);                                   \
        r23 = __hfma2(u2h(wh.w), b23h, r23);                                   \
        (DST)[(uint32_t)col*SLH + q*2    ] = h2u(r01);                         \
        (DST)[(uint32_t)col*SLH + q*2 + 1] = h2u(r23);                         \
    }

    // ---- prologue: gather+store tap 0; issue tap 1 loads
#pragma unroll
    for (int i = 0; i < 2; i++) {
        int p = gp0 + i*4 + cs;
        int2 id = sIdx2[p*KK];
        vs[i][0] = gxp[(size_t)id.x*8];
        vs[i][1] = gxp[(size_t)id.y*8];
    }
#pragma unroll
    for (int i = 0; i < 2; i++) {
        int p   = gp0 + i*4 + cs;
        int col = gcol0 + i*4 + cs;
        COMBINE_STORE(sB, i, p*KK)
    }
#pragma unroll
    for (int i = 0; i < 2; i++) {
        int p = gp0 + i*4 + cs;
        int2 id = sIdx2[p*KK + 1];
        vs[i][0] = gxp[(size_t)id.x*8];
        vs[i][1] = gxp[(size_t)id.y*8];
    }
    __syncthreads();

    // ---- main loop: 9 taps, deep pipeline
#pragma unroll
    for (int k = 0; k < KK; k++) {
        // MMA tap k (buf k&1): A loaded inline (L1-hot), 2 k16-steps x 4 n-groups
        {
            const uint32_t bufb = (uint32_t)(k & 1) * (NCOLS*SLH);
#pragma unroll
            for (int h = 0; h < 2; h++) {
                uint4 A = gwA[(k*2 + h)*32];
#pragma unroll
                for (int g = 0; g < 4; g++) {
                    uint32_t b0 = sB[bufb + bOff[g] + h*8];
                    uint32_t b1 = sB[bufb + bOff[g] + h*8 + 4];
                    asm volatile(
                        "mma.sync.aligned.m16n8k16.row.col.f32.f16.f16.f32 "
                        "{%0,%1,%2,%3}, {%4,%5,%6,%7}, {%8,%9}, {%0,%1,%2,%3};"
                        : "+f"(d[g][0]), "+f"(d[g][1]), "+f"(d[g][2]), "+f"(d[g][3])
                        : "r"(A.x), "r"(A.y), "r"(A.z), "r"(A.w), "r"(b0), "r"(b1));
                }
            }
        }
        if (k + 1 < KK) {
            // combine tap k+1 (loads issued one full stage ago) + store
            uint32_t* dstb = sB + (uint32_t)((k + 1) & 1)*(NCOLS*SLH);
#pragma unroll
            for (int i = 0; i < 2; i++) {
                int p   = gp0 + i*4 + cs;
                int col = gcol0 + i*4 + cs;
                COMBINE_STORE(dstb, i, p*KK + k + 1)
            }
            // issue tap k+2 loads into freed vs
            if (k + 2 < KK) {
#pragma unroll
                for (int i = 0; i < 2; i++) {
                    int p = gp0 + i*4 + cs;
                    int2 id = sIdx2[p*KK + k + 2];
                    vs[i][0] = gxp[(size_t)id.x*8];
                    vs[i][1] = gxp[(size_t)id.y*8];
                }
            }
            __syncthreads();
        }
    }

    // ---- epilogue: D row = output channel o, col = (b, pixel)
    {
        int o0 = mw*16 + (lane >> 2);
        float bias0 = sBias[o0];
        float bias1 = sBias[o0 + 8];
#pragma unroll
        for (int g = 0; g < 4; g++) {
            int n  = g*8 + (lane & 3)*2;
            int bb = n >> 4;
            int p  = n & 15;
            float* op = out + ((size_t)(bb*COUT + o0))*OHW + pix0 + p;
            *(float2*)op = make_float2(d[g][0] + bias0, d[g][1] + bias0);
            *(float2*)(op + (size_t)8*OHW) = make_float2(d[g][2] + bias1, d[g][3] + bias1);
        }
    }
#undef COMBINE_STORE
}

extern "C" void kernel_launch(void* const* d_in, const int* in_sizes, int n_in,
                              void* d_out, int out_size) {
    const float* x    = (const float*)d_in[0];
    const float* w    = (const float*)d_in[1];
    const float* bias = (const float*)d_in[2];
    const float* smap = (const float*)d_in[3];
    float* out = (float*)d_out;

    transpose_kernel<<<dim3(HWSZ/32, 3), 256>>>(x, w);   // y==2 slice does weights
    mapped_conv_kernel<<<OHW/TPIX, NTHR>>>(bias, smap, out);
}

// round 17
// speedup vs baseline: 2.2003x; 1.0264x over previous
#include <cuda_runtime.h>
#include <cuda_fp16.h>
#include <cstdint>

#define Bb     2
#define CIN    32
#define COUT   64
#define KK     9
#define HH     256
#define WW     512
#define HWSZ   (HH*WW)        // 131072
#define OHW    (HH*WW)        // 131072
#define CK     (CIN*KK)       // 288
#define NKS16  (CK/16)        // 18 k16-steps
#define PBE    (Bb*HWSZ/2)    // 131072 pair-entries per parity block

#define TPIX   32             // pixels per tile
#define NCOLS  64             // gemm N = 32 pix * 2 batch
#define SLH    20             // sB half2-word stride per col (conflict-free frag reads)
#define NTHR   128

// scratch: x as x-pair-interleaved fp16 [parity][B][H][W/2] (128B entries:
//   entry half2[c] = (v[x0][c], v[x0+1][c]) ), weights as fp16 m16n8k16 A-fragments
__device__ __align__(16) uint4 g_xp[2*PBE*8];
__device__ __align__(16) uint4 g_wfragA[4*NKS16*32];

__device__ __forceinline__ uint32_t h2u(__half2 h) {
    union { __half2 h; uint32_t u; } c; c.h = h; return c.u;
}
__device__ __forceinline__ __half2 u2h(uint32_t u) {
    union { uint32_t u; __half2 h; } c; c.u = u; return c.h;
}

// ------- transpose x -> pair-interleaved fp16; wt fragment bake on y==2 -------
__global__ void transpose_kernel(const float* __restrict__ x,
                                 const float* __restrict__ w) {
    __shared__ float tile[32][36];     // [c][hw 0..32]
    int b   = blockIdx.y;
    int tid = threadIdx.x;
    if (b == 2) {
        int i = blockIdx.x*256 + tid;
        if (i < 4*NKS16*32) {
            int lane = i & 31;
            int ks   = (i >> 5) % NKS16;
            int mg   = i / (NKS16*32);
            int l2 = lane >> 2, l1 = lane & 3;
            float v[8];
#pragma unroll
            for (int r = 0; r < 2; r++)
#pragma unroll
            for (int kk2 = 0; kk2 < 2; kk2++)
#pragma unroll
            for (int e = 0; e < 2; e++) {
                int o  = mg*16 + l2 + r*8;
                int ck = ks*16 + l1*2 + kk2*8 + e;
                int c = ck & 31, k = ck >> 5;
                v[r + kk2*4 + e*2] = w[(o*CIN + c)*KK + k];
            }
            uint4 pk;
            pk.x = h2u(__floats2half2_rn(v[0], v[2]));
            pk.y = h2u(__floats2half2_rn(v[1], v[3]));
            pk.z = h2u(__floats2half2_rn(v[4], v[6]));
            pk.w = h2u(__floats2half2_rn(v[5], v[7]));
            g_wfragA[i] = pk;
        }
        return;
    }
    int hw0 = blockIdx.x * 32;
    {
        int c = tid >> 3, q = tid & 7;
        float4 v = ((const float4*)x)[(((size_t)(b*CIN + c))*HWSZ + hw0)/4 + q];
        *(float4*)&tile[c][q*4] = v;
        if (q == 0) {   // 33rd column (clamped at plane end; used only w/ weight 0)
            size_t src = (size_t)(b*CIN + c)*HWSZ + hw0 + 32;
            if (hw0 + 32 >= HWSZ) src = (size_t)(b*CIN + c)*HWSZ + HWSZ - 1;
            tile[c][32] = x[src];
        }
    }
    __syncthreads();
    {
        int par = tid >> 7, j = (tid >> 3) & 15, q = tid & 7;
        int x0l = 2*j + par;
        int c0  = q*4;
        uint4 pk;
        pk.x = h2u(__floats2half2_rn(tile[c0+0][x0l], tile[c0+0][x0l+1]));
        pk.y = h2u(__floats2half2_rn(tile[c0+1][x0l], tile[c0+1][x0l+1]));
        pk.z = h2u(__floats2half2_rn(tile[c0+2][x0l], tile[c0+2][x0l+1]));
        pk.w = h2u(__floats2half2_rn(tile[c0+3][x0l], tile[c0+3][x0l+1]));
        size_t e = (size_t)par*PBE + (((size_t)b*HWSZ + hw0 + x0l) >> 1);
        g_xp[e*8 + q] = pk;
    }
}

// ------------- main: paired fp16 gather + m32n32 warp-tile f16 mma, 5 CTAs/SM -------------
__global__ void __launch_bounds__(NTHR, 5)
mapped_conv_kernel(const float* __restrict__ bias,
                   const float* __restrict__ smap,
                   float* __restrict__ out)
{
    __shared__ uint32_t sB[2*NCOLS*SLH];   // 2560 u32, double-buffered half2 sampled tile
    __shared__ int2   sIdx2[TPIX*KK];      // 288: pair-entry indices (y0,x0pair),(y1,x0pair)
    __shared__ uint4  sWgtH[TPIX*KK];      // 288: 4 duplicated-half2 bilinear weights
    __shared__ float  sBias[COUT];

    const int tid  = threadIdx.x;
    const int w    = tid >> 5;             // 0..3
    const int lane = tid & 31;
    const int pix0 = blockIdx.x * TPIX;

    if (tid < COUT) sBias[tid] = bias[tid];

    // bilinear tables: task t = p*9+k, 288 tasks
    for (int t = tid; t < TPIX*KK; t += NTHR) {
        int p = t / KK, k = t - p*KK;
        float2 sxy = ((const float2*)smap)[(pix0 + p)*KK + k];
        float bx = floorf(sxy.x), by = floorf(sxy.y);
        float fx = sxy.x - bx,    fy = sxy.y - by;
        int x0 = (int)bx, y0 = (int)by;
        int x0c = min(max(x0, 0), WW-1);   // pair (x0c, x0c+1); x0c==511 -> w01==0
        int y0c = min(max(y0, 0), HH-1);
        int y1c = min(y0 + 1, HH-1);
        int par = x0c & 1;
        sIdx2[t] = make_int2(par*PBE + ((y0c*WW + x0c) >> 1),
                             par*PBE + ((y1c*WW + x0c) >> 1));
        uint4 wh;
        wh.x = h2u(__float2half2_rn((1.f-fx)*(1.f-fy)));
        wh.y = h2u(__float2half2_rn(fx*(1.f-fy)));
        wh.z = h2u(__float2half2_rn((1.f-fx)*fy));
        wh.w = h2u(__float2half2_rn(fx*fy));
        sWgtH[t] = wh;
    }

    // gather mapping: warp w -> 16 cols (col = b*32 + p); lane = q(8 ch-quads) x cs(4)
    const int gb_b  = w >> 1;
    const int gcol0 = w * 16;
    const int gp0   = (w & 1) * 16;
    const int q     = lane & 7;
    const int cs    = lane >> 3;
    const uint4* __restrict__ gxp = g_xp + (size_t)gb_b*(HWSZ/2)*8 + q;

    // mma mapping: warp -> m32 (mw = w&1: m-groups mw*2, mw*2+1) x n32 (nw = w>>1)
    const int mw = w & 1;
    const int nw = w >> 1;
    uint32_t bOff[4];
#pragma unroll
    for (int g = 0; g < 4; g++)
        bOff[g] = (uint32_t)(nw*32 + g*8 + (lane >> 2))*SLH + (lane & 3);

    const uint4* __restrict__ gwA0 = g_wfragA + (uint32_t)((mw*2    )*NKS16)*32 + lane;
    const uint4* __restrict__ gwA1 = g_wfragA + (uint32_t)((mw*2 + 1)*NKS16)*32 + lane;

    float d[2][4][4];
#pragma unroll
    for (int r = 0; r < 2; r++)
#pragma unroll
    for (int g = 0; g < 4; g++)
#pragma unroll
    for (int j = 0; j < 4; j++) d[r][g][j] = 0.f;

    uint4 vs[4][2];      // [col-iter][y-corner]: 4 half2 = 4 ch x (x0,x1)

    __syncthreads();     // tables ready

#define COMBINE_STORE(DST, VI, WIDX)                                           \
    {                                                                          \
        uint4 wh = sWgtH[WIDX];                                                \
        uint4 vA = vs[VI][0], vB = vs[VI][1];                                  \
        __half2 a01l = __lows2half2(u2h(vA.x), u2h(vA.y));                     \
        __half2 a01h = __highs2half2(u2h(vA.x), u2h(vA.y));                    \
        __half2 a23l = __lows2half2(u2h(vA.z), u2h(vA.w));                     \
        __half2 a23h = __highs2half2(u2h(vA.z), u2h(vA.w));                    \
        __half2 b01l = __lows2half2(u2h(vB.x), u2h(vB.y));                     \
        __half2 b01h = __highs2half2(u2h(vB.x), u2h(vB.y));                    \
        __half2 b23l = __lows2half2(u2h(vB.z), u2h(vB.w));                     \
        __half2 b23h = __highs2half2(u2h(vB.z), u2h(vB.w));                    \
        __half2 r01 = __hmul2(u2h(wh.x), a01l);                                \
        r01 = __hfma2(u2h(wh.y), a01h, r01);                                   \
        r01 = __hfma2(u2h(wh.z), b01l, r01);                                   \
        r01 = __hfma2(u2h(wh.w), b01h, r01);                                   \
        __half2 r23 = __hmul2(u2h(wh.x), a23l);                                \
        r23 = __hfma2(u2h(wh.y), a23h, r23);                                   \
        r23 = __hfma2(u2h(wh.z), b23l, r23);                                   \
        r23 = __hfma2(u2h(wh.w), b23h, r23);                                   \
        (DST)[(uint32_t)col*SLH + q*2    ] = h2u(r01);                         \
        (DST)[(uint32_t)col*SLH + q*2 + 1] = h2u(r23);                         \
    }

    // ---- prologue: gather+store tap 0; issue tap 1 loads
#pragma unroll
    for (int i = 0; i < 4; i++) {
        int p = gp0 + i*4 + cs;
        int2 id = sIdx2[p*KK];
        vs[i][0] = gxp[(size_t)id.x*8];
        vs[i][1] = gxp[(size_t)id.y*8];
    }
#pragma unroll
    for (int i = 0; i < 4; i++) {
        int p   = gp0 + i*4 + cs;
        int col = gcol0 + i*4 + cs;
        COMBINE_STORE(sB, i, p*KK)
    }
#pragma unroll
    for (int i = 0; i < 4; i++) {
        int p = gp0 + i*4 + cs;
        int2 id = sIdx2[p*KK + 1];
        vs[i][0] = gxp[(size_t)id.x*8];
        vs[i][1] = gxp[(size_t)id.y*8];
    }
    __syncthreads();

    // ---- main loop: 9 taps, deep pipeline
#pragma unroll
    for (int k = 0; k < KK; k++) {
        // MMA tap k (buf k&1): A inline (L1-hot); B frags reused across both m-groups
        {
            const uint32_t bufb = (uint32_t)(k & 1) * (NCOLS*SLH);
#pragma unroll
            for (int h = 0; h < 2; h++) {
                uint4 A0 = gwA0[(k*2 + h)*32];
                uint4 A1 = gwA1[(k*2 + h)*32];
#pragma unroll
                for (int g = 0; g < 4; g++) {
                    uint32_t b0 = sB[bufb + bOff[g] + h*8];
                    uint32_t b1 = sB[bufb + bOff[g] + h*8 + 4];
                    asm volatile(
                        "mma.sync.aligned.m16n8k16.row.col.f32.f16.f16.f32 "
                        "{%0,%1,%2,%3}, {%4,%5,%6,%7}, {%8,%9}, {%0,%1,%2,%3};"
                        : "+f"(d[0][g][0]), "+f"(d[0][g][1]), "+f"(d[0][g][2]), "+f"(d[0][g][3])
                        : "r"(A0.x), "r"(A0.y), "r"(A0.z), "r"(A0.w), "r"(b0), "r"(b1));
                    asm volatile(
                        "mma.sync.aligned.m16n8k16.row.col.f32.f16.f16.f32 "
                        "{%0,%1,%2,%3}, {%4,%5,%6,%7}, {%8,%9}, {%0,%1,%2,%3};"
                        : "+f"(d[1][g][0]), "+f"(d[1][g][1]), "+f"(d[1][g][2]), "+f"(d[1][g][3])
                        : "r"(A1.x), "r"(A1.y), "r"(A1.z), "r"(A1.w), "r"(b0), "r"(b1));
                }
            }
        }
        if (k + 1 < KK) {
            // combine tap k+1 (loads issued one full stage ago) + store
            uint32_t* dstb = sB + (uint32_t)((k + 1) & 1)*(NCOLS*SLH);
#pragma unroll
            for (int i = 0; i < 4; i++) {
                int p   = gp0 + i*4 + cs;
                int col = gcol0 + i*4 + cs;
                COMBINE_STORE(dstb, i, p*KK + k + 1)
            }
            // issue tap k+2 loads into freed vs
            if (k + 2 < KK) {
#pragma unroll
                for (int i = 0; i < 4; i++) {
                    int p = gp0 + i*4 + cs;
                    int2 id = sIdx2[p*KK + k + 2];
                    vs[i][0] = gxp[(size_t)id.x*8];
                    vs[i][1] = gxp[(size_t)id.y*8];
                }
            }
            __syncthreads();
        }
    }

    // ---- epilogue: D row = output channel o, col = (b, pixel); b == nw here
    {
#pragma unroll
        for (int r = 0; r < 2; r++) {
            int o0 = (mw*2 + r)*16 + (lane >> 2);
            float bias0 = sBias[o0];
            float bias1 = sBias[o0 + 8];
#pragma unroll
            for (int g = 0; g < 4; g++) {
                int n  = nw*32 + g*8 + (lane & 3)*2;
                int bb = n >> 5;
                int p  = n & 31;
                float* op = out + ((size_t)(bb*COUT + o0))*OHW + pix0 + p;
                *(float2*)op = make_float2(d[r][g][0] + bias0, d[r][g][1] + bias0);
                *(float2*)(op + (size_t)8*OHW) = make_float2(d[r][g][2] + bias1, d[r][g][3] + bias1);
            }
        }
    }
#undef COMBINE_STORE
}

extern "C" void kernel_launch(void* const* d_in, const int* in_sizes, int n_in,
                              void* d_out, int out_size) {
    const float* x    = (const float*)d_in[0];
    const float* w    = (const float*)d_in[1];
    const float* bias = (const float*)d_in[2];
    const float* smap = (const float*)d_in[3];
    float* out = (float*)d_out;

    transpose_kernel<<<dim3(HWSZ/32, 3), 256>>>(x, w);   // y==2 slice does weights
    mapped_conv_kernel<<<OHW/TPIX, NTHR>>>(bias, smap, out);
}